// round 10
// baseline (speedup 1.0000x reference)
#include <cuda_runtime.h>
#include <cuda_bf16.h>
#include <cstdint>

// ---------------------------------------------------------------------------
// MeshUpConv: 3x SplineConv (kernel 3x3, degree 2, open spline) on GB300.
//
// R9 -> R10: GEMM moved to int8 tensor cores (mma.m16n8k32.s8.s32) with
// 16-bit dynamic fixed point:
//   x ~ sx[row]*(Xh*256 + Xl),  W ~ sw[col]*(Wh*256 + Wl)   (s8 pieces)
//   D = sx*sw*(65536*S1 + 256*S2),  S1 = Xh*Wh,  S2 = Xh*Wl + Xl*Wh
// 3 IMMA per K=32 chunk vs 12 HMMA per K=64 -> 2x fewer tensor instructions.
// Edge pass + counting sort unchanged (R9).
// ---------------------------------------------------------------------------

#define NMAX  50000
#define EMAX  400000
#define CKOUT 288          // K * C_OUT = 9 * 32
#define NCOLS 320          // 288 Y cols + 32 self cols

__device__ float g_Y[(size_t)NMAX * CKOUT];
__device__ float g_agg1[(size_t)NMAX * 32];
__device__ float g_agg2[(size_t)NMAX * 32];

// sort scratch
__device__ int    g_hist[NMAX];
__device__ int    g_off[NMAX];
__device__ int    g_bsum[128];
__device__ int2   g_se[EMAX];     // sorted (src, dst)
__device__ float2 g_sp[EMAX];     // sorted pseudo

// ---- helpers --------------------------------------------------------------
__device__ __forceinline__ void mma_s8(int* c,
                                       uint32_t a0, uint32_t a1, uint32_t a2, uint32_t a3,
                                       uint32_t b0, uint32_t b1) {
    asm("mma.sync.aligned.m16n8k32.row.col.s32.s8.s8.s32 "
        "{%0,%1,%2,%3}, {%4,%5,%6,%7}, {%8,%9}, {%0,%1,%2,%3};"
        : "+r"(c[0]), "+r"(c[1]), "+r"(c[2]), "+r"(c[3])
        : "r"(a0), "r"(a1), "r"(a2), "r"(a3), "r"(b0), "r"(b1));
}
__device__ __forceinline__ void ldsm_x4(uint32_t& r0, uint32_t& r1,
                                        uint32_t& r2, uint32_t& r3, uint32_t a) {
    asm volatile("ldmatrix.sync.aligned.m8n8.x4.shared.b16 {%0,%1,%2,%3}, [%4];"
                 : "=r"(r0), "=r"(r1), "=r"(r2), "=r"(r3) : "r"(a));
}
__device__ __forceinline__ void ldsm_x2(uint32_t& r0, uint32_t& r1, uint32_t a) {
    asm volatile("ldmatrix.sync.aligned.m8n8.x2.shared.b16 {%0,%1}, [%2];"
                 : "=r"(r0), "=r"(r1) : "r"(a));
}
__device__ __forceinline__ uint32_t smem_addr(const void* p) {
    return (uint32_t)__cvta_generic_to_shared(p);
}
__device__ __forceinline__ uint32_t pack4(int b0, int b1, int b2, int b3) {
    return (uint32_t)(uint8_t)b0 | ((uint32_t)(uint8_t)b1 << 8)
         | ((uint32_t)(uint8_t)b2 << 16) | ((uint32_t)(uint8_t)b3 << 24);
}

// SMEM layout (bytes). Row stride AW=20 words (64B data + 16B pad):
// ldmatrix banks (20*r)%32 are a permutation over 8 rows -> conflict-free.
#define AW 20
#define SM_SXA  0                         // 64 floats
#define SM_SWB  256                       // 320 floats
#define SM_BIA  1536                      // 32 floats
#define SM_AH   1664                      // 64 rows *80B = 5120
#define SM_AL   (SM_AH + 5120)            // 6784
#define SM_BH   (SM_AL + 5120)            // 11904, 320 rows *80B = 25600
#define SM_BL   (SM_BH + 25600)           // 37504
#define SMEM_G  (SM_BL + 25600)           // 63104

// ---------------------------------------------------------------------------
// int8 GEMM: per 64-node tile, D[64, 320] = A[64,64] @ Bw[64,320].
// 16 warps = 2(M) x 8(N); warp = 32 rows (2 mt) x 40 cols (5 nt).
// ---------------------------------------------------------------------------
template<int CA, int CB, bool RELU_A, int CIN_W>
__global__ __launch_bounds__(512)
void gemm_i8(const float* __restrict__ xa, const float* __restrict__ xb,
             const float* __restrict__ W, const float* __restrict__ root,
             const float* __restrict__ bias,
             float* __restrict__ Y, float* __restrict__ agg, int n_nodes)
{
    extern __shared__ __align__(16) char smem[];
    float*    sxa = reinterpret_cast<float*>(smem + SM_SXA);
    float*    swb = reinterpret_cast<float*>(smem + SM_SWB);
    float*    bsm = reinterpret_cast<float*>(smem + SM_BIA);
    uint32_t* Ah  = reinterpret_cast<uint32_t*>(smem + SM_AH);
    uint32_t* Al  = reinterpret_cast<uint32_t*>(smem + SM_AL);
    uint32_t* Bh  = reinterpret_cast<uint32_t*>(smem + SM_BH);
    uint32_t* Bl  = reinterpret_cast<uint32_t*>(smem + SM_BL);

    const int tid    = threadIdx.x;
    const int wid    = tid >> 5;
    const int lane   = tid & 31;
    const int warp_m = wid >> 3;        // 0..1 -> rows [32*warp_m, +32)
    const int warp_n = wid & 7;         // 0..7 -> cols [40*warp_n, +40)
    const int jj     = tid & 7;         // 8 threads per staged row
    constexpr int KSTEPS = CIN_W / 32;

    // quantize 8 floats -> hi/lo words + scale; group = 8 lanes (aligned).
    auto quant8 = [&](const float v[8], uint32_t* dstH, uint32_t* dstL,
                      int rowword, float* scale_out, bool lead) {
        float m = 0.0f;
        #pragma unroll
        for (int i = 0; i < 8; i++) m = fmaxf(m, fabsf(v[i]));
        #pragma unroll
        for (int o = 1; o < 8; o <<= 1) m = fmaxf(m, __shfl_xor_sync(0xffffffffu, m, o));
        const float inv = (m > 0.0f) ? 32512.0f / m : 0.0f;
        int vh[8], vl[8];
        #pragma unroll
        for (int i = 0; i < 8; i++) {
            const int q16 = __float2int_rn(v[i] * inv);
            vh[i] = (q16 + 128) >> 8;
            vl[i] = q16 - (vh[i] << 8);
        }
        dstH[rowword + 2*jj]     = pack4(vh[0], vh[1], vh[2], vh[3]);
        dstH[rowword + 2*jj + 1] = pack4(vh[4], vh[5], vh[6], vh[7]);
        dstL[rowword + 2*jj]     = pack4(vl[0], vl[1], vl[2], vl[3]);
        dstL[rowword + 2*jj + 1] = pack4(vl[4], vl[5], vl[6], vl[7]);
        if (lead) *scale_out = (m > 0.0f) ? m / 32512.0f : 0.0f;
    };

    // ---- Stage B once per CTA (row r = output col; k padded to 64).
    for (int r = tid >> 3; r < NCOLS; r += 64) {
        float v[8];
        #pragma unroll
        for (int mth = 0; mth < 8; mth++) {
            const int i = 8 * jj + mth;
            float val = 0.0f;
            if (i < CIN_W) {
                if (r < CKOUT) {
                    const int kk = r >> 5, cc = r & 31;
                    val = W[(kk * CIN_W + i) * 32 + cc];
                } else {
                    val = root[i * 32 + (r - CKOUT)];
                }
            }
            v[mth] = val;
        }
        quant8(v, Bh, Bl, r * AW, &swb[r], jj == 0);
    }
    if (tid < 32) bsm[tid] = bias[tid];
    __syncthreads();

    // ldmatrix per-lane base addresses.
    const uint32_t aoffB = 4u * ((uint32_t)(warp_m * 32 + (lane & 15)) * AW) + (lane >> 4) * 16;
    const uint32_t boffB = 4u * ((uint32_t)(warp_n * 40 + (lane & 7))  * AW) + ((lane >> 3) & 1) * 16;
    const uint32_t aH = smem_addr(Ah) + aoffB;
    const uint32_t aL = smem_addr(Al) + aoffB;
    const uint32_t bH = smem_addr(Bh) + boffB;
    const uint32_t bL = smem_addr(Bl) + boffB;

    const int ntiles = (n_nodes + 63) >> 6;

    for (int t = blockIdx.x; t < ntiles; t += gridDim.x) {
        const int n0 = t << 6;

        // ---- Stage A tile: 64 rows x 64 ch (relu/concat fused), quantized.
        {
            const int row = tid >> 3;
            const int n   = n0 + row;
            float v[8];
            const int i0 = 8 * jj;
            if (n < n_nodes && i0 < CA) {
                const float4 p0 = *reinterpret_cast<const float4*>(xa + (size_t)n * CA + i0);
                const float4 p1 = *reinterpret_cast<const float4*>(xa + (size_t)n * CA + i0 + 4);
                v[0]=p0.x; v[1]=p0.y; v[2]=p0.z; v[3]=p0.w;
                v[4]=p1.x; v[5]=p1.y; v[6]=p1.z; v[7]=p1.w;
                if (RELU_A) {
                    #pragma unroll
                    for (int i = 0; i < 8; i++) v[i] = fmaxf(v[i], 0.0f);
                }
            } else if (n < n_nodes && CB > 0 && i0 < CA + CB) {
                const float4 p0 = *reinterpret_cast<const float4*>(xb + (size_t)n * CB + (i0 - CA));
                const float4 p1 = *reinterpret_cast<const float4*>(xb + (size_t)n * CB + (i0 - CA) + 4);
                v[0]=p0.x; v[1]=p0.y; v[2]=p0.z; v[3]=p0.w;
                v[4]=p1.x; v[5]=p1.y; v[6]=p1.z; v[7]=p1.w;
            } else {
                #pragma unroll
                for (int i = 0; i < 8; i++) v[i] = 0.0f;
            }
            quant8(v, Ah, Al, row * AW, &sxa[row], jj == 0);
        }
        __syncthreads();

        // ---- Compute: accH/accM[2 mt][5 nt][4]
        int accH[2][5][4], accM[2][5][4];
        #pragma unroll
        for (int mt = 0; mt < 2; mt++)
            #pragma unroll
            for (int nt = 0; nt < 5; nt++)
                #pragma unroll
                for (int j = 0; j < 4; j++) { accH[mt][nt][j] = 0; accM[mt][nt][j] = 0; }

        #pragma unroll
        for (int ks = 0; ks < KSTEPS; ks++) {
            const uint32_t ko = 32u * ks;            // 32 bytes per K-chunk
            uint32_t ah[2][4], al[2][4];
            #pragma unroll
            for (int mt = 0; mt < 2; mt++) {
                const uint32_t mo = 4u * mt * 16 * AW;
                ldsm_x4(ah[mt][0], ah[mt][1], ah[mt][2], ah[mt][3], aH + mo + ko);
                ldsm_x4(al[mt][0], al[mt][1], al[mt][2], al[mt][3], aL + mo + ko);
            }
            #pragma unroll
            for (int nt = 0; nt < 5; nt++) {
                const uint32_t no = 4u * nt * 8 * AW;
                uint32_t bh0, bh1, bl0, bl1;
                ldsm_x2(bh0, bh1, bH + no + ko);
                ldsm_x2(bl0, bl1, bL + no + ko);
                #pragma unroll
                for (int mt = 0; mt < 2; mt++) {
                    mma_s8(accH[mt][nt], ah[mt][0], ah[mt][1], ah[mt][2], ah[mt][3], bh0, bh1);
                    mma_s8(accM[mt][nt], ah[mt][0], ah[mt][1], ah[mt][2], ah[mt][3], bl0, bl1);
                    mma_s8(accM[mt][nt], al[mt][0], al[mt][1], al[mt][2], al[mt][3], bh0, bh1);
                }
            }
        }

        // ---- Epilogue: dequant + store. c-frag: rows (q, q+8), cols (2lkp, +1).
        const int q   = lane >> 2;
        const int lkp = lane & 3;
        #pragma unroll
        for (int mt = 0; mt < 2; mt++) {
            const int rowA = warp_m * 32 + mt * 16 + q;
            const int r0 = n0 + rowA;
            const int r1 = r0 + 8;
            const float sx0 = sxa[rowA], sx1 = sxa[rowA + 8];
            #pragma unroll
            for (int nt = 0; nt < 5; nt++) {
                const int col0 = warp_n * 40 + nt * 8 + 2 * lkp;
                const float sw0 = swb[col0], sw1 = swb[col0 + 1];
                const float f00 = (65536.0f * (float)accH[mt][nt][0] + 256.0f * (float)accM[mt][nt][0]) * sx0 * sw0;
                const float f01 = (65536.0f * (float)accH[mt][nt][1] + 256.0f * (float)accM[mt][nt][1]) * sx0 * sw1;
                const float f10 = (65536.0f * (float)accH[mt][nt][2] + 256.0f * (float)accM[mt][nt][2]) * sx1 * sw0;
                const float f11 = (65536.0f * (float)accH[mt][nt][3] + 256.0f * (float)accM[mt][nt][3]) * sx1 * sw1;
                if (col0 < CKOUT) {
                    if (r0 < n_nodes)
                        *reinterpret_cast<float2*>(Y + (size_t)r0 * CKOUT + col0) = make_float2(f00, f01);
                    if (r1 < n_nodes)
                        *reinterpret_cast<float2*>(Y + (size_t)r1 * CKOUT + col0) = make_float2(f10, f11);
                } else {
                    const int a = col0 - CKOUT;
                    const float b0v = bsm[a], b1v = bsm[a + 1];
                    if (r0 < n_nodes)
                        *reinterpret_cast<float2*>(agg + (size_t)r0 * 32 + a) = make_float2(f00 + b0v, f01 + b1v);
                    if (r1 < n_nodes)
                        *reinterpret_cast<float2*>(agg + (size_t)r1 * 32 + a) = make_float2(f10 + b0v, f11 + b1v);
                }
            }
        }
        __syncthreads();
    }
}

// ---------------------------------------------------------------------------
// Counting sort of edges by src (once per launch, reused by 3 edge passes).
// ---------------------------------------------------------------------------
__global__ void hist_zero(int n) {
    const int i = blockIdx.x * blockDim.x + threadIdx.x;
    if (i < n) g_hist[i] = 0;
}
__global__ void hist_kernel(const int* __restrict__ ei, int n_edges) {
    const int e = blockIdx.x * blockDim.x + threadIdx.x;
    if (e < n_edges) atomicAdd(&g_hist[ei[e]], 1);
}
__global__ void scan1(int n) {
    __shared__ int s[512];
    const int tid = threadIdx.x;
    const int b   = blockIdx.x * 512 + tid;
    const int v   = (b < n) ? g_hist[b] : 0;
    s[tid] = v;
    __syncthreads();
    #pragma unroll
    for (int off = 1; off < 512; off <<= 1) {
        int t = (tid >= off) ? s[tid - off] : 0;
        __syncthreads();
        s[tid] += t;
        __syncthreads();
    }
    if (b < n) g_off[b] = s[tid] - v;        // exclusive, block-local
    if (tid == 511) g_bsum[blockIdx.x] = s[511];   // raw block total
}
__global__ void scan3(int n) {
    __shared__ int pref;
    const int bid = blockIdx.x;
    if (threadIdx.x < 32) {
        int s = 0;
        for (int i = threadIdx.x; i < bid; i += 32) s += g_bsum[i];
        #pragma unroll
        for (int o = 16; o; o >>= 1) s += __shfl_down_sync(0xffffffffu, s, o);
        if (threadIdx.x == 0) pref = s;
    }
    __syncthreads();
    const int b = bid * 512 + threadIdx.x;
    if (b < n) g_off[b] += pref;
}
__global__ void scatter_kernel(const int* __restrict__ ei,
                               const float* __restrict__ pseudo, int n_edges) {
    const int e = blockIdx.x * blockDim.x + threadIdx.x;
    if (e >= n_edges) return;
    const int src = ei[e];
    const int dst = ei[n_edges + e];
    const int pos = atomicAdd(&g_off[src], 1);
    g_se[pos] = make_int2(src, dst);
    g_sp[pos] = reinterpret_cast<const float2*>(pseudo)[e];
}

// ---------------------------------------------------------------------------
// Edge kernel (sorted by src): 8 lanes per edge, 4 channels per lane.
// ---------------------------------------------------------------------------
__global__ __launch_bounds__(256)
void edge_kernel(const float* __restrict__ Y, float* __restrict__ agg,
                 int n_edges, int n_nodes)
{
    const int t   = blockIdx.x * 256 + threadIdx.x;
    const int e   = t >> 3;
    const int sub = t & 7;
    if (e >= n_edges) return;

    const int2   sd = g_se[e];
    const float2 p  = g_sp[e];
    if ((unsigned)sd.x >= (unsigned)n_nodes || (unsigned)sd.y >= (unsigned)n_nodes) return;

    const float q00 = 0.5f * (1.0f - p.x) * (1.0f - p.x);
    const float q01 = -p.x * p.x + p.x + 0.5f;
    const float q02 = 0.5f * p.x * p.x;
    const float q10 = 0.5f * (1.0f - p.y) * (1.0f - p.y);
    const float q11 = -p.y * p.y + p.y + 0.5f;
    const float q12 = 0.5f * p.y * p.y;

    const float b0 = q10 * q00, b1 = q10 * q01, b2 = q10 * q02;
    const float b3 = q11 * q00, b4 = q11 * q01, b5 = q11 * q02;
    const float b6 = q12 * q00, b7 = q12 * q01, b8 = q12 * q02;

    const float4* y = reinterpret_cast<const float4*>(Y + (size_t)sd.x * CKOUT + sub * 4);
    const float4 y0 = y[0*8], y1 = y[1*8], y2 = y[2*8];
    const float4 y3 = y[3*8], y4 = y[4*8], y5 = y[5*8];
    const float4 y6 = y[6*8], y7 = y[7*8], y8 = y[8*8];

    float4 a;
    a.x = b0*y0.x + b1*y1.x + b2*y2.x + b3*y3.x + b4*y4.x + b5*y5.x + b6*y6.x + b7*y7.x + b8*y8.x;
    a.y = b0*y0.y + b1*y1.y + b2*y2.y + b3*y3.y + b4*y4.y + b5*y5.y + b6*y6.y + b7*y7.y + b8*y8.y;
    a.z = b0*y0.z + b1*y1.z + b2*y2.z + b3*y3.z + b4*y4.z + b5*y5.z + b6*y6.z + b7*y7.z + b8*y8.z;
    a.w = b0*y0.w + b1*y1.w + b2*y2.w + b3*y3.w + b4*y4.w + b5*y5.w + b6*y6.w + b7*y7.w + b8*y8.w;

    float* dp = agg + (size_t)sd.y * 32 + sub * 4;
    asm volatile("red.global.add.v4.f32 [%0], {%1, %2, %3, %4};"
                 :: "l"(dp), "f"(a.x), "f"(a.y), "f"(a.z), "f"(a.w) : "memory");
}

__global__ void relu_kernel(float* __restrict__ d, int n)
{
    const int i = blockIdx.x * blockDim.x + threadIdx.x;
    if (i < n) d[i] = fmaxf(d[i], 0.0f);
}

// ---------------------------------------------------------------------------
extern "C" void kernel_launch(void* const* d_in, const int* in_sizes, int n_in,
                              void* d_out, int out_size)
{
    const float* x      = (const float*)d_in[0];
    const int*   ei     = (const int*)d_in[1];     // int64 in ref -> int32 in harness
    const float* pseudo = (const float*)d_in[2];
    const float* skip   = (const float*)d_in[3];
    const float* W1     = (const float*)d_in[4];
    const float* root1  = (const float*)d_in[5];
    const float* b1     = (const float*)d_in[6];
    const float* W2     = (const float*)d_in[7];
    const float* root2  = (const float*)d_in[8];
    const float* b2     = (const float*)d_in[9];

    const int N = in_sizes[0] / 64;
    const int E = in_sizes[1] / 2;
    float* out = (float*)d_out;

    float *Y, *agg1, *agg2;
    cudaGetSymbolAddress((void**)&Y,    g_Y);
    cudaGetSymbolAddress((void**)&agg1, g_agg1);
    cudaGetSymbolAddress((void**)&agg2, g_agg2);

    cudaFuncSetAttribute(gemm_i8<64, 0,  false, 64>,
                         cudaFuncAttributeMaxDynamicSharedMemorySize, SMEM_G);
    cudaFuncSetAttribute(gemm_i8<32, 32, true,  64>,
                         cudaFuncAttributeMaxDynamicSharedMemorySize, SMEM_G);
    cudaFuncSetAttribute(gemm_i8<32, 0,  true,  32>,
                         cudaFuncAttributeMaxDynamicSharedMemorySize, SMEM_G);

    const int gemm_grid = 148;
    const int edge_grid = (E * 8 + 255) / 256;
    const int NB        = (N + 511) / 512;

    // ---- Sort edges by src (once; reused by all 3 edge passes).
    hist_zero<<<NB, 512>>>(N);
    hist_kernel<<<(E + 255) / 256, 256>>>(ei, E);
    scan1<<<NB, 512>>>(N);
    scan3<<<NB, 512>>>(N);
    scatter_kernel<<<(E + 255) / 256, 256>>>(ei, pseudo, E);

    // Layer 1: x[N,64] -> agg1
    gemm_i8<64, 0, false, 64><<<gemm_grid, 512, SMEM_G>>>(x, nullptr, W1, root1, b1, Y, agg1, N);
    edge_kernel<<<edge_grid, 256>>>(Y, agg1, E, N);

    // Layer 2: concat(relu(agg1), skip)[N,64] -> agg2   (same W1/root1/b1)
    gemm_i8<32, 32, true, 64><<<gemm_grid, 512, SMEM_G>>>(agg1, skip, W1, root1, b1, Y, agg2, N);
    edge_kernel<<<edge_grid, 256>>>(Y, agg2, E, N);

    // Layer 3: relu(agg2)[N,32] -> d_out  (K = 32 -> 1 k-step)
    gemm_i8<32, 0, true, 32><<<gemm_grid, 512, SMEM_G>>>(agg2, nullptr, W2, root2, b2, Y, out, N);
    edge_kernel<<<edge_grid, 256>>>(Y, out, E, N);

    relu_kernel<<<(N * 32 + 255) / 256, 256>>>(out, N * 32);
}

// round 11
// speedup vs baseline: 1.3892x; 1.3892x over previous
#include <cuda_runtime.h>
#include <cuda_bf16.h>
#include <cuda_fp16.h>
#include <cstdint>

// ---------------------------------------------------------------------------
// MeshUpConv: 3x SplineConv (kernel 3x3, degree 2, open spline) on GB300.
//
// R10 -> R11: int8 GEMM reverted (regressed: IMMA not faster than HMMA here,
// quant staging expensive). Base = R9 bf16x3 ldmatrix GEMM.
// NEW: Y stored as fp16 (self term / aggregation stay fp32):
//   * edge gather bytes halve (1152 -> 576 B/row)  [L2-byte-bound pass]
//   * edge restructured to 4 lanes/edge x 8 ch (uint4 = 8 halves per k):
//     per-edge LSU requests 80 -> 44.
// ---------------------------------------------------------------------------

#define NMAX  50000
#define EMAX  400000
#define CKOUT 288          // K * C_OUT = 9 * 32
#define NCOLS 320          // 288 Y cols + 32 self cols

__device__ __half g_Y[(size_t)NMAX * CKOUT];
__device__ float  g_agg1[(size_t)NMAX * 32];
__device__ float  g_agg2[(size_t)NMAX * 32];

// sort scratch
__device__ int    g_hist[NMAX];
__device__ int    g_off[NMAX];
__device__ int    g_bsum[128];
__device__ int2   g_se[EMAX];     // sorted (src, dst)
__device__ float2 g_sp[EMAX];     // sorted pseudo

// ---- helpers --------------------------------------------------------------
__device__ __forceinline__ uint32_t pack_bf16(float a, float b) {
    __nv_bfloat162 t = __floats2bfloat162_rn(a, b);
    return *reinterpret_cast<uint32_t*>(&t);
}
__device__ __forceinline__ void split_hl(float v, float& h, float& l) {
    __nv_bfloat16 bh = __float2bfloat16_rn(v);
    h = __bfloat162float(bh);
    l = v - h;
}
__device__ __forceinline__ void mma_bf16(float* c,
                                         uint32_t a0, uint32_t a1, uint32_t a2, uint32_t a3,
                                         uint32_t b0, uint32_t b1) {
    asm("mma.sync.aligned.m16n8k16.row.col.f32.bf16.bf16.f32 "
        "{%0,%1,%2,%3}, {%4,%5,%6,%7}, {%8,%9}, {%0,%1,%2,%3};"
        : "+f"(c[0]), "+f"(c[1]), "+f"(c[2]), "+f"(c[3])
        : "r"(a0), "r"(a1), "r"(a2), "r"(a3), "r"(b0), "r"(b1));
}
__device__ __forceinline__ void ldsm_x4(uint32_t& r0, uint32_t& r1,
                                        uint32_t& r2, uint32_t& r3, uint32_t a) {
    asm volatile("ldmatrix.sync.aligned.m8n8.x4.shared.b16 {%0,%1,%2,%3}, [%4];"
                 : "=r"(r0), "=r"(r1), "=r"(r2), "=r"(r3) : "r"(a));
}
__device__ __forceinline__ void ldsm_x2(uint32_t& r0, uint32_t& r1, uint32_t a) {
    asm volatile("ldmatrix.sync.aligned.m8n8.x2.shared.b16 {%0,%1}, [%2];"
                 : "=r"(r0), "=r"(r1) : "r"(a));
}
__device__ __forceinline__ uint32_t smem_addr(const void* p) {
    return (uint32_t)__cvta_generic_to_shared(p);
}

// SMEM layout. Stride 36 words: bank=(4q+r)%32 -> conflict-free fragments.
#define ASTR 36
#define SM_BIAS 0
#define SM_A_HI 128
#define SM_A_LO (SM_A_HI + 128 * ASTR * 4)       // 18560
#define SM_B_HI (SM_A_LO + 128 * ASTR * 4)       // 36992
#define SM_B_LO (SM_B_HI + 320 * ASTR * 4)       // 83072
#define SMEM_BYTES (SM_B_LO + 320 * ASTR * 4)    // 129152

// ---------------------------------------------------------------------------
// mma.sync GEMM: per 128-node tile, D[128, 320] = A[128,64] @ Bw[64,320].
// 16 warps = 4(M) x 4(N); warp = 32 rows x 80 cols. bf16x3, fp32 accum.
// Y cols stored as fp16; self cols (agg) stored fp32.
// ---------------------------------------------------------------------------
template<int CA, int CB, bool RELU_A, int CIN_W>
__global__ __launch_bounds__(512)
void gemm_mma(const float* __restrict__ xa, const float* __restrict__ xb,
              const float* __restrict__ W, const float* __restrict__ root,
              const float* __restrict__ bias,
              __half* __restrict__ Y, float* __restrict__ agg, int n_nodes)
{
    extern __shared__ __align__(16) char smem[];
    uint32_t* Ah = reinterpret_cast<uint32_t*>(smem + SM_A_HI);
    uint32_t* Al = reinterpret_cast<uint32_t*>(smem + SM_A_LO);
    uint32_t* Bh = reinterpret_cast<uint32_t*>(smem + SM_B_HI);
    uint32_t* Bl = reinterpret_cast<uint32_t*>(smem + SM_B_LO);
    float*    bs = reinterpret_cast<float*>(smem + SM_BIAS);

    const int tid    = threadIdx.x;
    const int wid    = tid >> 5;
    const int lane   = tid & 31;
    const int warp_m = wid >> 2;
    const int warp_n = wid & 3;
    constexpr int KSTEPS = CIN_W / 16;

    // ---- Stage B once per CTA.
    for (int idx = tid; idx < NCOLS * 32; idx += 512) {
        const int r  = idx >> 5;
        const int kp = idx & 31;
        const int i0 = 2 * kp, i1 = i0 + 1;
        float v0 = 0.0f, v1 = 0.0f;
        if (i0 < CIN_W) {
            if (r < CKOUT) {
                const int kk = r >> 5, cc = r & 31;
                v0 = W[(kk * CIN_W + i0) * 32 + cc];
                v1 = W[(kk * CIN_W + i1) * 32 + cc];
            } else {
                v0 = root[i0 * 32 + (r - CKOUT)];
                v1 = root[i1 * 32 + (r - CKOUT)];
            }
        }
        float h0, l0, h1, l1;
        split_hl(v0, h0, l0); split_hl(v1, h1, l1);
        Bh[r * ASTR + kp] = pack_bf16(h0, h1);
        Bl[r * ASTR + kp] = pack_bf16(l0, l1);
    }
    if (tid < 32) bs[tid] = bias[tid];
    __syncthreads();

    const uint32_t aoffw = (uint32_t)(warp_m * 32 + (lane & 15)) * ASTR + (lane >> 4) * 4;
    const uint32_t boffw = (uint32_t)(warp_n * 80 + (lane & 7)) * ASTR + ((lane >> 3) & 1) * 4;
    const uint32_t aH = smem_addr(Ah) + 4 * aoffw;
    const uint32_t aL = smem_addr(Al) + 4 * aoffw;
    const uint32_t bH = smem_addr(Bh) + 4 * boffw;
    const uint32_t bL = smem_addr(Bl) + 4 * boffw;

    const int ntiles = (n_nodes + 127) >> 7;

    for (int t = blockIdx.x; t < ntiles; t += gridDim.x) {
        const int n0 = t << 7;

        // ---- Stage A tile (relu/concat fused).
        for (int idx = tid; idx < 128 * 32; idx += 512) {
            const int row = idx >> 5;
            const int kp  = idx & 31;
            const int n   = n0 + row;
            const int i0  = 2 * kp, i1 = i0 + 1;
            float v0 = 0.0f, v1 = 0.0f;
            if (n < n_nodes) {
                if (i0 < CA) {
                    v0 = xa[(size_t)n * CA + i0];
                    v1 = xa[(size_t)n * CA + i1];
                    if (RELU_A) { v0 = fmaxf(v0, 0.0f); v1 = fmaxf(v1, 0.0f); }
                } else if (CB > 0 && i0 < CA + CB) {
                    v0 = xb[(size_t)n * CB + (i0 - CA)];
                    v1 = xb[(size_t)n * CB + (i1 - CA)];
                }
            }
            float h0, l0, h1, l1;
            split_hl(v0, h0, l0); split_hl(v1, h1, l1);
            Ah[row * ASTR + kp] = pack_bf16(h0, h1);
            Al[row * ASTR + kp] = pack_bf16(l0, l1);
        }
        __syncthreads();

        float acc[2][10][4];
        #pragma unroll
        for (int mt = 0; mt < 2; mt++)
            #pragma unroll
            for (int nt = 0; nt < 10; nt++)
                #pragma unroll
                for (int j = 0; j < 4; j++) acc[mt][nt][j] = 0.0f;

        #pragma unroll
        for (int ks = 0; ks < KSTEPS; ks++) {
            const uint32_t ko = 4u * ks * 8;
            uint32_t ah[2][4], al[2][4];
            #pragma unroll
            for (int mt = 0; mt < 2; mt++) {
                const uint32_t mo = 4u * mt * 16 * ASTR;
                ldsm_x4(ah[mt][0], ah[mt][1], ah[mt][2], ah[mt][3], aH + mo + ko);
                ldsm_x4(al[mt][0], al[mt][1], al[mt][2], al[mt][3], aL + mo + ko);
            }
            #pragma unroll
            for (int nt = 0; nt < 10; nt++) {
                const uint32_t no = 4u * nt * 8 * ASTR;
                uint32_t bh0, bh1, bl0, bl1;
                ldsm_x2(bh0, bh1, bH + no + ko);
                ldsm_x2(bl0, bl1, bL + no + ko);
                #pragma unroll
                for (int mt = 0; mt < 2; mt++) {
                    mma_bf16(acc[mt][nt], ah[mt][0], ah[mt][1], ah[mt][2], ah[mt][3], bh0, bh1);
                    mma_bf16(acc[mt][nt], ah[mt][0], ah[mt][1], ah[mt][2], ah[mt][3], bl0, bl1);
                    mma_bf16(acc[mt][nt], al[mt][0], al[mt][1], al[mt][2], al[mt][3], bh0, bh1);
                }
            }
        }

        // ---- Epilogue: Y cols -> fp16 (half2 store); self cols -> fp32 agg.
        const int q   = lane >> 2;
        const int lkp = lane & 3;
        #pragma unroll
        for (int mt = 0; mt < 2; mt++) {
            const int r0 = n0 + warp_m * 32 + mt * 16 + q;
            const int r1 = r0 + 8;
            #pragma unroll
            for (int nt = 0; nt < 10; nt++) {
                const int col0 = warp_n * 80 + nt * 8 + 2 * lkp;
                if (col0 < CKOUT) {
                    if (r0 < n_nodes)
                        *reinterpret_cast<__half2*>(Y + (size_t)r0 * CKOUT + col0)
                            = __floats2half2_rn(acc[mt][nt][0], acc[mt][nt][1]);
                    if (r1 < n_nodes)
                        *reinterpret_cast<__half2*>(Y + (size_t)r1 * CKOUT + col0)
                            = __floats2half2_rn(acc[mt][nt][2], acc[mt][nt][3]);
                } else {
                    const int a = col0 - CKOUT;
                    const float b0v = bs[a], b1v = bs[a + 1];
                    if (r0 < n_nodes)
                        *reinterpret_cast<float2*>(agg + (size_t)r0 * 32 + a)
                            = make_float2(acc[mt][nt][0] + b0v, acc[mt][nt][1] + b1v);
                    if (r1 < n_nodes)
                        *reinterpret_cast<float2*>(agg + (size_t)r1 * 32 + a)
                            = make_float2(acc[mt][nt][2] + b0v, acc[mt][nt][3] + b1v);
                }
            }
        }
        __syncthreads();
    }
}

// ---------------------------------------------------------------------------
// Counting sort of edges by src (once per launch, reused by 3 edge passes).
// ---------------------------------------------------------------------------
__global__ void hist_zero(int n) {
    const int i = blockIdx.x * blockDim.x + threadIdx.x;
    if (i < n) g_hist[i] = 0;
}
__global__ void hist_kernel(const int* __restrict__ ei, int n_edges) {
    const int e = blockIdx.x * blockDim.x + threadIdx.x;
    if (e < n_edges) atomicAdd(&g_hist[ei[e]], 1);
}
__global__ void scan1(int n) {
    __shared__ int s[512];
    const int tid = threadIdx.x;
    const int b   = blockIdx.x * 512 + tid;
    const int v   = (b < n) ? g_hist[b] : 0;
    s[tid] = v;
    __syncthreads();
    #pragma unroll
    for (int off = 1; off < 512; off <<= 1) {
        int t = (tid >= off) ? s[tid - off] : 0;
        __syncthreads();
        s[tid] += t;
        __syncthreads();
    }
    if (b < n) g_off[b] = s[tid] - v;
    if (tid == 511) g_bsum[blockIdx.x] = s[511];
}
__global__ void scan3(int n) {
    __shared__ int pref;
    const int bid = blockIdx.x;
    if (threadIdx.x < 32) {
        int s = 0;
        for (int i = threadIdx.x; i < bid; i += 32) s += g_bsum[i];
        #pragma unroll
        for (int o = 16; o; o >>= 1) s += __shfl_down_sync(0xffffffffu, s, o);
        if (threadIdx.x == 0) pref = s;
    }
    __syncthreads();
    const int b = bid * 512 + threadIdx.x;
    if (b < n) g_off[b] += pref;
}
__global__ void scatter_kernel(const int* __restrict__ ei,
                               const float* __restrict__ pseudo, int n_edges) {
    const int e = blockIdx.x * blockDim.x + threadIdx.x;
    if (e >= n_edges) return;
    const int src = ei[e];
    const int dst = ei[n_edges + e];
    const int pos = atomicAdd(&g_off[src], 1);
    g_se[pos] = make_int2(src, dst);
    g_sp[pos] = reinterpret_cast<const float2*>(pseudo)[e];
}

// ---------------------------------------------------------------------------
// Edge kernel (sorted by src): 4 lanes/edge, 8 channels/lane.
// Per lane: 9 x LDG.128 (uint4 = 8 fp16) + 2 x red.v4.f32.
// ---------------------------------------------------------------------------
__global__ __launch_bounds__(256)
void edge_kernel(const __half* __restrict__ Y, float* __restrict__ agg,
                 int n_edges, int n_nodes)
{
    const int t   = blockIdx.x * 256 + threadIdx.x;
    const int e   = t >> 2;
    const int sub = t & 3;            // channels [8*sub, 8*sub+8)
    if (e >= n_edges) return;

    const int2   sd = g_se[e];
    const float2 p  = g_sp[e];
    if ((unsigned)sd.x >= (unsigned)n_nodes || (unsigned)sd.y >= (unsigned)n_nodes) return;

    const float q00 = 0.5f * (1.0f - p.x) * (1.0f - p.x);
    const float q01 = -p.x * p.x + p.x + 0.5f;
    const float q02 = 0.5f * p.x * p.x;
    const float q10 = 0.5f * (1.0f - p.y) * (1.0f - p.y);
    const float q11 = -p.y * p.y + p.y + 0.5f;
    const float q12 = 0.5f * p.y * p.y;

    const float bb[9] = { q10*q00, q10*q01, q10*q02,
                          q11*q00, q11*q01, q11*q02,
                          q12*q00, q12*q01, q12*q02 };

    // 8 halves per k-slice; k-slice stride = 32 halves = 4 uint4.
    const uint4* y = reinterpret_cast<const uint4*>(Y + (size_t)sd.x * CKOUT + sub * 8);

    float acc[8] = {0,0,0,0,0,0,0,0};
    #pragma unroll
    for (int k = 0; k < 9; k++) {
        const uint4 qv = y[k * 4];
        const float bk = bb[k];
        const float2 f0 = __half22float2(*reinterpret_cast<const __half2*>(&qv.x));
        const float2 f1 = __half22float2(*reinterpret_cast<const __half2*>(&qv.y));
        const float2 f2 = __half22float2(*reinterpret_cast<const __half2*>(&qv.z));
        const float2 f3 = __half22float2(*reinterpret_cast<const __half2*>(&qv.w));
        acc[0] += bk * f0.x; acc[1] += bk * f0.y;
        acc[2] += bk * f1.x; acc[3] += bk * f1.y;
        acc[4] += bk * f2.x; acc[5] += bk * f2.y;
        acc[6] += bk * f3.x; acc[7] += bk * f3.y;
    }

    float* dp = agg + (size_t)sd.y * 32 + sub * 8;
    asm volatile("red.global.add.v4.f32 [%0], {%1, %2, %3, %4};"
                 :: "l"(dp), "f"(acc[0]), "f"(acc[1]), "f"(acc[2]), "f"(acc[3]) : "memory");
    asm volatile("red.global.add.v4.f32 [%0], {%1, %2, %3, %4};"
                 :: "l"(dp + 4), "f"(acc[4]), "f"(acc[5]), "f"(acc[6]), "f"(acc[7]) : "memory");
}

__global__ void relu_kernel(float* __restrict__ d, int n)
{
    const int i = blockIdx.x * blockDim.x + threadIdx.x;
    if (i < n) d[i] = fmaxf(d[i], 0.0f);
}

// ---------------------------------------------------------------------------
extern "C" void kernel_launch(void* const* d_in, const int* in_sizes, int n_in,
                              void* d_out, int out_size)
{
    const float* x      = (const float*)d_in[0];
    const int*   ei     = (const int*)d_in[1];     // int64 in ref -> int32 in harness
    const float* pseudo = (const float*)d_in[2];
    const float* skip   = (const float*)d_in[3];
    const float* W1     = (const float*)d_in[4];
    const float* root1  = (const float*)d_in[5];
    const float* b1     = (const float*)d_in[6];
    const float* W2     = (const float*)d_in[7];
    const float* root2  = (const float*)d_in[8];
    const float* b2     = (const float*)d_in[9];

    const int N = in_sizes[0] / 64;
    const int E = in_sizes[1] / 2;
    float* out = (float*)d_out;

    __half* Y;
    float *agg1, *agg2;
    cudaGetSymbolAddress((void**)&Y,    g_Y);
    cudaGetSymbolAddress((void**)&agg1, g_agg1);
    cudaGetSymbolAddress((void**)&agg2, g_agg2);

    cudaFuncSetAttribute(gemm_mma<64, 0,  false, 64>,
                         cudaFuncAttributeMaxDynamicSharedMemorySize, SMEM_BYTES);
    cudaFuncSetAttribute(gemm_mma<32, 32, true,  64>,
                         cudaFuncAttributeMaxDynamicSharedMemorySize, SMEM_BYTES);
    cudaFuncSetAttribute(gemm_mma<32, 0,  true,  32>,
                         cudaFuncAttributeMaxDynamicSharedMemorySize, SMEM_BYTES);

    const int gemm_grid = 148;
    const int edge_grid = (E * 4 + 255) / 256;
    const int NB        = (N + 511) / 512;

    // ---- Sort edges by src (once; reused by all 3 edge passes).
    hist_zero<<<NB, 512>>>(N);
    hist_kernel<<<(E + 255) / 256, 256>>>(ei, E);
    scan1<<<NB, 512>>>(N);
    scan3<<<NB, 512>>>(N);
    scatter_kernel<<<(E + 255) / 256, 256>>>(ei, pseudo, E);

    // Layer 1: x[N,64] -> agg1
    gemm_mma<64, 0, false, 64><<<gemm_grid, 512, SMEM_BYTES>>>(x, nullptr, W1, root1, b1, Y, agg1, N);
    edge_kernel<<<edge_grid, 256>>>(Y, agg1, E, N);

    // Layer 2: concat(relu(agg1), skip)[N,64] -> agg2   (same W1/root1/b1)
    gemm_mma<32, 32, true, 64><<<gemm_grid, 512, SMEM_BYTES>>>(agg1, skip, W1, root1, b1, Y, agg2, N);
    edge_kernel<<<edge_grid, 256>>>(Y, agg2, E, N);

    // Layer 3: relu(agg2)[N,32] -> d_out  (K = 32 -> 2 k-steps)
    gemm_mma<32, 0, true, 32><<<gemm_grid, 512, SMEM_BYTES>>>(agg2, nullptr, W2, root2, b2, Y, out, N);
    edge_kernel<<<edge_grid, 256>>>(Y, out, E, N);

    relu_kernel<<<(N * 32 + 255) / 256, 256>>>(out, N * 32);
}

// round 12
// speedup vs baseline: 1.4820x; 1.0668x over previous
#include <cuda_runtime.h>
#include <cuda_fp16.h>
#include <cstdint>

// ---------------------------------------------------------------------------
// MeshUpConv: 3x SplineConv (kernel 3x3, degree 2, open spline) on GB300.
//
// R11 -> R12: GEMM precision re-split for fewer tensor ops.
//   Old: X,W both bf16 hi+lo, 3 MMAs (XhWh + XhWl + XlWh).
//   New: A = fp16(X) single piece; B = W split fp16 hi+lo (W exact).
//        D = A*Wh + A*Wl  -> 2 MMAs per fragment (-33%), A staging halved.
//   Only new error = fp16 rounding of X (~1.4e-4 RMS, same scale as the
//   already-measured fp16-Y rounding). Y stays fp16; agg/self stay fp32.
// Edge pass (4 lanes/edge, uint4 fp16 gathers, red.v4) + sort unchanged.
// ---------------------------------------------------------------------------

#define NMAX  50000
#define EMAX  400000
#define CKOUT 288          // K * C_OUT = 9 * 32
#define NCOLS 320          // 288 Y cols + 32 self cols

__device__ __half g_Y[(size_t)NMAX * CKOUT];
__device__ float  g_agg1[(size_t)NMAX * 32];
__device__ float  g_agg2[(size_t)NMAX * 32];

// sort scratch
__device__ int    g_hist[NMAX];
__device__ int    g_off[NMAX];
__device__ int    g_bsum[128];
__device__ int2   g_se[EMAX];     // sorted (src, dst)
__device__ float2 g_sp[EMAX];     // sorted pseudo

// ---- helpers --------------------------------------------------------------
__device__ __forceinline__ uint32_t pack_f16(float a, float b) {
    __half2 t = __floats2half2_rn(a, b);
    return *reinterpret_cast<uint32_t*>(&t);
}
__device__ __forceinline__ void mma_f16(float* c,
                                        uint32_t a0, uint32_t a1, uint32_t a2, uint32_t a3,
                                        uint32_t b0, uint32_t b1) {
    asm("mma.sync.aligned.m16n8k16.row.col.f32.f16.f16.f32 "
        "{%0,%1,%2,%3}, {%4,%5,%6,%7}, {%8,%9}, {%0,%1,%2,%3};"
        : "+f"(c[0]), "+f"(c[1]), "+f"(c[2]), "+f"(c[3])
        : "r"(a0), "r"(a1), "r"(a2), "r"(a3), "r"(b0), "r"(b1));
}
__device__ __forceinline__ void ldsm_x4(uint32_t& r0, uint32_t& r1,
                                        uint32_t& r2, uint32_t& r3, uint32_t a) {
    asm volatile("ldmatrix.sync.aligned.m8n8.x4.shared.b16 {%0,%1,%2,%3}, [%4];"
                 : "=r"(r0), "=r"(r1), "=r"(r2), "=r"(r3) : "r"(a));
}
__device__ __forceinline__ void ldsm_x2(uint32_t& r0, uint32_t& r1, uint32_t a) {
    asm volatile("ldmatrix.sync.aligned.m8n8.x2.shared.b16 {%0,%1}, [%2];"
                 : "=r"(r0), "=r"(r1) : "r"(a));
}
__device__ __forceinline__ uint32_t smem_addr(const void* p) {
    return (uint32_t)__cvta_generic_to_shared(p);
}

// SMEM layout. Stride 36 words: bank=(4q+r)%32 -> conflict-free fragments.
// A: 128 rows x 32 kpairs (fp16 single); B: 320 rows x 32 kpairs, hi & lo.
#define ASTR 36
#define SM_BIAS 0
#define SM_A    128
#define SM_B_HI (SM_A + 128 * ASTR * 4)          // 18560
#define SM_B_LO (SM_B_HI + 320 * ASTR * 4)       // 64640
#define SMEM_BYTES (SM_B_LO + 320 * ASTR * 4)    // 110720

// ---------------------------------------------------------------------------
// mma.sync GEMM: per 128-node tile, D[128, 320] = A[128,64] @ Bw[64,320].
// 16 warps = 4(M) x 4(N); warp = 32 rows x 80 cols. fp16 A, fp16x2 W, fp32 acc.
// ---------------------------------------------------------------------------
template<int CA, int CB, bool RELU_A, int CIN_W>
__global__ __launch_bounds__(512)
void gemm_mma(const float* __restrict__ xa, const float* __restrict__ xb,
              const float* __restrict__ W, const float* __restrict__ root,
              const float* __restrict__ bias,
              __half* __restrict__ Y, float* __restrict__ agg, int n_nodes)
{
    extern __shared__ __align__(16) char smem[];
    uint32_t* Aa = reinterpret_cast<uint32_t*>(smem + SM_A);
    uint32_t* Bh = reinterpret_cast<uint32_t*>(smem + SM_B_HI);
    uint32_t* Bl = reinterpret_cast<uint32_t*>(smem + SM_B_LO);
    float*    bs = reinterpret_cast<float*>(smem + SM_BIAS);

    const int tid    = threadIdx.x;
    const int wid    = tid >> 5;
    const int lane   = tid & 31;
    const int warp_m = wid >> 2;
    const int warp_n = wid & 3;
    constexpr int KSTEPS = CIN_W / 16;

    // ---- Stage B once per CTA: W split into fp16 hi + lo (exact).
    for (int idx = tid; idx < NCOLS * 32; idx += 512) {
        const int r  = idx >> 5;
        const int kp = idx & 31;
        const int i0 = 2 * kp, i1 = i0 + 1;
        float v0 = 0.0f, v1 = 0.0f;
        if (i0 < CIN_W) {
            if (r < CKOUT) {
                const int kk = r >> 5, cc = r & 31;
                v0 = W[(kk * CIN_W + i0) * 32 + cc];
                v1 = W[(kk * CIN_W + i1) * 32 + cc];
            } else {
                v0 = root[i0 * 32 + (r - CKOUT)];
                v1 = root[i1 * 32 + (r - CKOUT)];
            }
        }
        const float h0 = __half2float(__float2half_rn(v0));
        const float h1 = __half2float(__float2half_rn(v1));
        Bh[r * ASTR + kp] = pack_f16(h0, h1);
        Bl[r * ASTR + kp] = pack_f16(v0 - h0, v1 - h1);
    }
    if (tid < 32) bs[tid] = bias[tid];
    __syncthreads();

    const uint32_t aoffw = (uint32_t)(warp_m * 32 + (lane & 15)) * ASTR + (lane >> 4) * 4;
    const uint32_t boffw = (uint32_t)(warp_n * 80 + (lane & 7)) * ASTR + ((lane >> 3) & 1) * 4;
    const uint32_t aA = smem_addr(Aa) + 4 * aoffw;
    const uint32_t bH = smem_addr(Bh) + 4 * boffw;
    const uint32_t bL = smem_addr(Bl) + 4 * boffw;

    const int ntiles = (n_nodes + 127) >> 7;

    for (int t = blockIdx.x; t < ntiles; t += gridDim.x) {
        const int n0 = t << 7;

        // ---- Stage A tile: fp16 single piece (relu/concat fused).
        for (int idx = tid; idx < 128 * 32; idx += 512) {
            const int row = idx >> 5;
            const int kp  = idx & 31;
            const int n   = n0 + row;
            const int i0  = 2 * kp, i1 = i0 + 1;
            float v0 = 0.0f, v1 = 0.0f;
            if (n < n_nodes) {
                if (i0 < CA) {
                    v0 = xa[(size_t)n * CA + i0];
                    v1 = xa[(size_t)n * CA + i1];
                    if (RELU_A) { v0 = fmaxf(v0, 0.0f); v1 = fmaxf(v1, 0.0f); }
                } else if (CB > 0 && i0 < CA + CB) {
                    v0 = xb[(size_t)n * CB + (i0 - CA)];
                    v1 = xb[(size_t)n * CB + (i1 - CA)];
                }
            }
            Aa[row * ASTR + kp] = pack_f16(v0, v1);
        }
        __syncthreads();

        float acc[2][10][4];
        #pragma unroll
        for (int mt = 0; mt < 2; mt++)
            #pragma unroll
            for (int nt = 0; nt < 10; nt++)
                #pragma unroll
                for (int j = 0; j < 4; j++) acc[mt][nt][j] = 0.0f;

        #pragma unroll
        for (int ks = 0; ks < KSTEPS; ks++) {
            const uint32_t ko = 4u * ks * 8;
            uint32_t a_[2][4];
            #pragma unroll
            for (int mt = 0; mt < 2; mt++) {
                const uint32_t mo = 4u * mt * 16 * ASTR;
                ldsm_x4(a_[mt][0], a_[mt][1], a_[mt][2], a_[mt][3], aA + mo + ko);
            }
            #pragma unroll
            for (int nt = 0; nt < 10; nt++) {
                const uint32_t no = 4u * nt * 8 * ASTR;
                uint32_t bh0, bh1, bl0, bl1;
                ldsm_x2(bh0, bh1, bH + no + ko);
                ldsm_x2(bl0, bl1, bL + no + ko);
                #pragma unroll
                for (int mt = 0; mt < 2; mt++) {
                    mma_f16(acc[mt][nt], a_[mt][0], a_[mt][1], a_[mt][2], a_[mt][3], bh0, bh1);
                    mma_f16(acc[mt][nt], a_[mt][0], a_[mt][1], a_[mt][2], a_[mt][3], bl0, bl1);
                }
            }
        }

        // ---- Epilogue: Y cols -> fp16 (half2 store); self cols -> fp32 agg.
        const int q   = lane >> 2;
        const int lkp = lane & 3;
        #pragma unroll
        for (int mt = 0; mt < 2; mt++) {
            const int r0 = n0 + warp_m * 32 + mt * 16 + q;
            const int r1 = r0 + 8;
            #pragma unroll
            for (int nt = 0; nt < 10; nt++) {
                const int col0 = warp_n * 80 + nt * 8 + 2 * lkp;
                if (col0 < CKOUT) {
                    if (r0 < n_nodes)
                        *reinterpret_cast<__half2*>(Y + (size_t)r0 * CKOUT + col0)
                            = __floats2half2_rn(acc[mt][nt][0], acc[mt][nt][1]);
                    if (r1 < n_nodes)
                        *reinterpret_cast<__half2*>(Y + (size_t)r1 * CKOUT + col0)
                            = __floats2half2_rn(acc[mt][nt][2], acc[mt][nt][3]);
                } else {
                    const int a = col0 - CKOUT;
                    const float b0v = bs[a], b1v = bs[a + 1];
                    if (r0 < n_nodes)
                        *reinterpret_cast<float2*>(agg + (size_t)r0 * 32 + a)
                            = make_float2(acc[mt][nt][0] + b0v, acc[mt][nt][1] + b1v);
                    if (r1 < n_nodes)
                        *reinterpret_cast<float2*>(agg + (size_t)r1 * 32 + a)
                            = make_float2(acc[mt][nt][2] + b0v, acc[mt][nt][3] + b1v);
                }
            }
        }
        __syncthreads();
    }
}

// ---------------------------------------------------------------------------
// Counting sort of edges by src (once per launch, reused by 3 edge passes).
// ---------------------------------------------------------------------------
__global__ void hist_zero(int n) {
    const int i = blockIdx.x * blockDim.x + threadIdx.x;
    if (i < n) g_hist[i] = 0;
}
__global__ void hist_kernel(const int* __restrict__ ei, int n_edges) {
    const int e = blockIdx.x * blockDim.x + threadIdx.x;
    if (e < n_edges) atomicAdd(&g_hist[ei[e]], 1);
}
__global__ void scan1(int n) {
    __shared__ int s[512];
    const int tid = threadIdx.x;
    const int b   = blockIdx.x * 512 + tid;
    const int v   = (b < n) ? g_hist[b] : 0;
    s[tid] = v;
    __syncthreads();
    #pragma unroll
    for (int off = 1; off < 512; off <<= 1) {
        int t = (tid >= off) ? s[tid - off] : 0;
        __syncthreads();
        s[tid] += t;
        __syncthreads();
    }
    if (b < n) g_off[b] = s[tid] - v;
    if (tid == 511) g_bsum[blockIdx.x] = s[511];
}
__global__ void scan3(int n) {
    __shared__ int pref;
    const int bid = blockIdx.x;
    if (threadIdx.x < 32) {
        int s = 0;
        for (int i = threadIdx.x; i < bid; i += 32) s += g_bsum[i];
        #pragma unroll
        for (int o = 16; o; o >>= 1) s += __shfl_down_sync(0xffffffffu, s, o);
        if (threadIdx.x == 0) pref = s;
    }
    __syncthreads();
    const int b = bid * 512 + threadIdx.x;
    if (b < n) g_off[b] += pref;
}
__global__ void scatter_kernel(const int* __restrict__ ei,
                               const float* __restrict__ pseudo, int n_edges) {
    const int e = blockIdx.x * blockDim.x + threadIdx.x;
    if (e >= n_edges) return;
    const int src = ei[e];
    const int dst = ei[n_edges + e];
    const int pos = atomicAdd(&g_off[src], 1);
    g_se[pos] = make_int2(src, dst);
    g_sp[pos] = reinterpret_cast<const float2*>(pseudo)[e];
}

// ---------------------------------------------------------------------------
// Edge kernel (sorted by src): 4 lanes/edge, 8 channels/lane.
// Per lane: 9 x LDG.128 (uint4 = 8 fp16) + 2 x red.v4.f32.
// ---------------------------------------------------------------------------
__global__ __launch_bounds__(256)
void edge_kernel(const __half* __restrict__ Y, float* __restrict__ agg,
                 int n_edges, int n_nodes)
{
    const int t   = blockIdx.x * 256 + threadIdx.x;
    const int e   = t >> 2;
    const int sub = t & 3;            // channels [8*sub, 8*sub+8)
    if (e >= n_edges) return;

    const int2   sd = g_se[e];
    const float2 p  = g_sp[e];
    if ((unsigned)sd.x >= (unsigned)n_nodes || (unsigned)sd.y >= (unsigned)n_nodes) return;

    const float q00 = 0.5f * (1.0f - p.x) * (1.0f - p.x);
    const float q01 = -p.x * p.x + p.x + 0.5f;
    const float q02 = 0.5f * p.x * p.x;
    const float q10 = 0.5f * (1.0f - p.y) * (1.0f - p.y);
    const float q11 = -p.y * p.y + p.y + 0.5f;
    const float q12 = 0.5f * p.y * p.y;

    const float bb[9] = { q10*q00, q10*q01, q10*q02,
                          q11*q00, q11*q01, q11*q02,
                          q12*q00, q12*q01, q12*q02 };

    const uint4* y = reinterpret_cast<const uint4*>(Y + (size_t)sd.x * CKOUT + sub * 8);

    float acc[8] = {0,0,0,0,0,0,0,0};
    #pragma unroll
    for (int k = 0; k < 9; k++) {
        const uint4 qv = y[k * 4];
        const float bk = bb[k];
        const float2 f0 = __half22float2(*reinterpret_cast<const __half2*>(&qv.x));
        const float2 f1 = __half22float2(*reinterpret_cast<const __half2*>(&qv.y));
        const float2 f2 = __half22float2(*reinterpret_cast<const __half2*>(&qv.z));
        const float2 f3 = __half22float2(*reinterpret_cast<const __half2*>(&qv.w));
        acc[0] += bk * f0.x; acc[1] += bk * f0.y;
        acc[2] += bk * f1.x; acc[3] += bk * f1.y;
        acc[4] += bk * f2.x; acc[5] += bk * f2.y;
        acc[6] += bk * f3.x; acc[7] += bk * f3.y;
    }

    float* dp = agg + (size_t)sd.y * 32 + sub * 8;
    asm volatile("red.global.add.v4.f32 [%0], {%1, %2, %3, %4};"
                 :: "l"(dp), "f"(acc[0]), "f"(acc[1]), "f"(acc[2]), "f"(acc[3]) : "memory");
    asm volatile("red.global.add.v4.f32 [%0], {%1, %2, %3, %4};"
                 :: "l"(dp + 4), "f"(acc[4]), "f"(acc[5]), "f"(acc[6]), "f"(acc[7]) : "memory");
}

__global__ void relu_kernel(float* __restrict__ d, int n)
{
    const int i = blockIdx.x * blockDim.x + threadIdx.x;
    if (i < n) d[i] = fmaxf(d[i], 0.0f);
}

// ---------------------------------------------------------------------------
extern "C" void kernel_launch(void* const* d_in, const int* in_sizes, int n_in,
                              void* d_out, int out_size)
{
    const float* x      = (const float*)d_in[0];
    const int*   ei     = (const int*)d_in[1];     // int64 in ref -> int32 in harness
    const float* pseudo = (const float*)d_in[2];
    const float* skip   = (const float*)d_in[3];
    const float* W1     = (const float*)d_in[4];
    const float* root1  = (const float*)d_in[5];
    const float* b1     = (const float*)d_in[6];
    const float* W2     = (const float*)d_in[7];
    const float* root2  = (const float*)d_in[8];
    const float* b2     = (const float*)d_in[9];

    const int N = in_sizes[0] / 64;
    const int E = in_sizes[1] / 2;
    float* out = (float*)d_out;

    __half* Y;
    float *agg1, *agg2;
    cudaGetSymbolAddress((void**)&Y,    g_Y);
    cudaGetSymbolAddress((void**)&agg1, g_agg1);
    cudaGetSymbolAddress((void**)&agg2, g_agg2);

    cudaFuncSetAttribute(gemm_mma<64, 0,  false, 64>,
                         cudaFuncAttributeMaxDynamicSharedMemorySize, SMEM_BYTES);
    cudaFuncSetAttribute(gemm_mma<32, 32, true,  64>,
                         cudaFuncAttributeMaxDynamicSharedMemorySize, SMEM_BYTES);
    cudaFuncSetAttribute(gemm_mma<32, 0,  true,  32>,
                         cudaFuncAttributeMaxDynamicSharedMemorySize, SMEM_BYTES);

    const int gemm_grid = 148;
    const int edge_grid = (E * 4 + 255) / 256;
    const int NB        = (N + 511) / 512;

    // ---- Sort edges by src (once; reused by all 3 edge passes).
    hist_zero<<<NB, 512>>>(N);
    hist_kernel<<<(E + 255) / 256, 256>>>(ei, E);
    scan1<<<NB, 512>>>(N);
    scan3<<<NB, 512>>>(N);
    scatter_kernel<<<(E + 255) / 256, 256>>>(ei, pseudo, E);

    // Layer 1: x[N,64] -> agg1
    gemm_mma<64, 0, false, 64><<<gemm_grid, 512, SMEM_BYTES>>>(x, nullptr, W1, root1, b1, Y, agg1, N);
    edge_kernel<<<edge_grid, 256>>>(Y, agg1, E, N);

    // Layer 2: concat(relu(agg1), skip)[N,64] -> agg2   (same W1/root1/b1)
    gemm_mma<32, 32, true, 64><<<gemm_grid, 512, SMEM_BYTES>>>(agg1, skip, W1, root1, b1, Y, agg2, N);
    edge_kernel<<<edge_grid, 256>>>(Y, agg2, E, N);

    // Layer 3: relu(agg2)[N,32] -> d_out  (K = 32 -> 2 k-steps)
    gemm_mma<32, 0, true, 32><<<gemm_grid, 512, SMEM_BYTES>>>(agg2, nullptr, W2, root2, b2, Y, out, N);
    edge_kernel<<<edge_grid, 256>>>(Y, out, E, N);

    relu_kernel<<<(N * 32 + 255) / 256, 256>>>(out, N * 32);
}